// round 1
// baseline (speedup 1.0000x reference)
#include <cuda_runtime.h>
#include <math.h>

#define Bb 2
#define Hh 48
#define Ww 48
#define Cc 256
#define NHh 8
#define HDd 32
#define Ll 2304          // 48*48
#define Rr (Bb*Ll)       // 4608
#define SCALING 0.17677669529663687f  // 32^-0.5

// scratch (no cudaMalloc allowed)
__device__ float g_q[Rr*Cc];
__device__ float g_k[Rr*Cc];
__device__ float g_v[Rr*Cc];
__device__ float g_attn[Rr*Cc];
__device__ float g_lepe[Rr*Cc];

// ---------------------------------------------------------------------------
// GEMM: out[r,c] = (A[r,:] (+A2[r,:])) @ W[:,c] + bias[c]; optional RoPE epilogue.
// mode 0: rope (q) ; mode 1: scale then rope (k) ; mode 2: plain
// BM=64, BN=64, BK=16, 256 threads, 4x4 microtile.
// ---------------------------------------------------------------------------
__global__ __launch_bounds__(256) void gemm_rope_kernel(
    const float* __restrict__ A, const float* __restrict__ A2,
    const float* __restrict__ W, const float* __restrict__ bias,
    const float* __restrict__ sinp, const float* __restrict__ cosp,
    float* __restrict__ out, int mode)
{
    __shared__ float xs[64][16];
    __shared__ float ws[16][68];

    int tid = threadIdx.x;
    int tx = tid & 15, ty = tid >> 4;
    int row0 = blockIdx.x * 64;
    int col0 = blockIdx.y * 64;

    float acc[4][4] = {};

    for (int kt = 0; kt < Cc; kt += 16) {
        // A tile: 64x16, one float4 per thread
        {
            int r = tid >> 2, kv = (tid & 3) * 4;
            float4 v4 = *reinterpret_cast<const float4*>(&A[(size_t)(row0 + r)*Cc + kt + kv]);
            if (A2) {
                float4 v2 = *reinterpret_cast<const float4*>(&A2[(size_t)(row0 + r)*Cc + kt + kv]);
                v4.x += v2.x; v4.y += v2.y; v4.z += v2.z; v4.w += v2.w;
            }
            *reinterpret_cast<float4*>(&xs[r][kv]) = v4;
        }
        // W tile: 16x64, one float4 per thread
        {
            int kr = tid >> 4, cv = (tid & 15) * 4;
            float4 v4 = *reinterpret_cast<const float4*>(&W[(size_t)(kt + kr)*Cc + col0 + cv]);
            *reinterpret_cast<float4*>(&ws[kr][cv]) = v4;
        }
        __syncthreads();
        #pragma unroll
        for (int kk = 0; kk < 16; ++kk) {
            float a[4], b[4];
            #pragma unroll
            for (int i = 0; i < 4; ++i) a[i] = xs[ty*4+i][kk];
            #pragma unroll
            for (int j = 0; j < 4; ++j) b[j] = ws[kk][tx*4+j];
            #pragma unroll
            for (int i = 0; i < 4; ++i)
                #pragma unroll
                for (int j = 0; j < 4; ++j)
                    acc[i][j] = fmaf(a[i], b[j], acc[i][j]);
        }
        __syncthreads();
    }

    int colb = col0 + tx*4;
    float bi[4];
    #pragma unroll
    for (int j = 0; j < 4; ++j) bi[j] = bias[colb + j];

    #pragma unroll
    for (int i = 0; i < 4; ++i) {
        int rg = row0 + ty*4 + i;
        float v[4];
        #pragma unroll
        for (int j = 0; j < 4; ++j) v[j] = acc[i][j] + bi[j];
        if (mode == 1) {
            #pragma unroll
            for (int j = 0; j < 4; ++j) v[j] *= SCALING;
        }
        if (mode <= 1) {
            int l = rg % Ll;
            int h0 = colb & 31;                     // hd index of first col (even)
            const float* sb = sinp + (size_t)l*HDd + h0;
            const float* cb = cosp + (size_t)l*HDd + h0;
            float s0=sb[0], s1=sb[1], s2=sb[2], s3=sb[3];
            float c0=cb[0], c1=cb[1], c2=cb[2], c3=cb[3];
            float e0 = v[0]*c0 - v[1]*s0;
            float o0 = v[1]*c1 + v[0]*s1;
            float e1 = v[2]*c2 - v[3]*s2;
            float o1 = v[3]*c3 + v[2]*s3;
            v[0]=e0; v[1]=o0; v[2]=e1; v[3]=o1;
        }
        float4 st = make_float4(v[0], v[1], v[2], v[3]);
        *reinterpret_cast<float4*>(&out[(size_t)rg*Cc + colb]) = st;
    }
}

// ---------------------------------------------------------------------------
// Depthwise 5x5 conv (LEPE) on g_v (NHWC == [b,l,c]) -> g_lepe
// ---------------------------------------------------------------------------
__global__ __launch_bounds__(256) void lepe_kernel(
    const float* __restrict__ wdw, const float* __restrict__ bdw)
{
    int idx = blockIdx.x * blockDim.x + threadIdx.x;
    if (idx >= Rr*Cc) return;
    int c  = idx & (Cc-1);
    int rl = idx >> 8;           // b*L + l
    int b  = rl / Ll;
    int l  = rl - b*Ll;
    int h  = l / Ww;
    int w  = l - h*Ww;

    float acc = bdw[c];
    #pragma unroll
    for (int kh = 0; kh < 5; ++kh) {
        int hh = h + kh - 2;
        if ((unsigned)hh >= (unsigned)Hh) continue;
        #pragma unroll
        for (int kw = 0; kw < 5; ++kw) {
            int ww2 = w + kw - 2;
            if ((unsigned)ww2 >= (unsigned)Ww) continue;
            acc = fmaf(g_v[((size_t)b*Ll + hh*Ww + ww2)*Cc + c],
                       wdw[(kh*5 + kw)*Cc + c], acc);
        }
    }
    g_lepe[idx] = acc;
}

// ---------------------------------------------------------------------------
// Flash attention with additive mask, fp32.
// Block: 256 threads, 64 query rows, KV tiles of 64. grid = (L/64, B*NH)
// grid.y: n = y>>1, b = y&1 (adjacent blocks share a head's mask slab -> L2 reuse)
// ---------------------------------------------------------------------------
__global__ __launch_bounds__(256) void attn_kernel(const float* __restrict__ mask)
{
    __shared__ float Qs[64][33];
    __shared__ float Ks[64][33];
    __shared__ float Vs[64][33];
    __shared__ float Ps[64][65];
    __shared__ float m_s[64], l_s[64], sc_s[64];

    int tid = threadIdx.x;
    int tx = tid & 15, ty = tid >> 4;
    int n = blockIdx.y >> 1;
    int b = blockIdx.y & 1;
    int l0 = blockIdx.x * 64;

    const float* qb = g_q + ((size_t)b*Ll)*Cc + n*HDd;
    const float* kb = g_k + ((size_t)b*Ll)*Cc + n*HDd;
    const float* vb = g_v + ((size_t)b*Ll)*Cc + n*HDd;
    const float* mb = mask + ((size_t)n*Ll + l0)*Ll;

    for (int j = tid; j < 64*32; j += 256) {
        int r = j >> 5, d = j & 31;
        Qs[r][d] = qb[(size_t)(l0 + r)*Cc + d];
    }
    if (tid < 64) { m_s[tid] = -1e30f; l_s[tid] = 0.f; }
    float o[4][2] = {};
    __syncthreads();

    for (int m0 = 0; m0 < Ll; m0 += 64) {
        for (int j = tid; j < 64*32; j += 256) {
            int r = j >> 5, d = j & 31;
            Ks[r][d] = kb[(size_t)(m0 + r)*Cc + d];
            Vs[r][d] = vb[(size_t)(m0 + r)*Cc + d];
        }
        __syncthreads();

        // S = Q @ K^T
        float acc[4][4] = {};
        #pragma unroll
        for (int d = 0; d < 32; ++d) {
            float a[4], bb[4];
            #pragma unroll
            for (int i = 0; i < 4; ++i) a[i] = Qs[ty*4+i][d];
            #pragma unroll
            for (int j = 0; j < 4; ++j) bb[j] = Ks[tx*4+j][d];
            #pragma unroll
            for (int i = 0; i < 4; ++i)
                #pragma unroll
                for (int j = 0; j < 4; ++j)
                    acc[i][j] = fmaf(a[i], bb[j], acc[i][j]);
        }
        // + mask, row-max
        float rmax[4];
        #pragma unroll
        for (int i = 0; i < 4; ++i) {
            const float* mrow = mb + (size_t)(ty*4+i)*Ll + m0 + tx*4;
            #pragma unroll
            for (int j = 0; j < 4; ++j) acc[i][j] += mrow[j];
            rmax[i] = fmaxf(fmaxf(acc[i][0], acc[i][1]), fmaxf(acc[i][2], acc[i][3]));
        }
        #pragma unroll
        for (int s = 8; s; s >>= 1)
            #pragma unroll
            for (int i = 0; i < 4; ++i)
                rmax[i] = fmaxf(rmax[i], __shfl_xor_sync(0xffffffffu, rmax[i], s));
        if (tx == 0) {
            #pragma unroll
            for (int i = 0; i < 4; ++i) {
                int r = ty*4+i;
                float mo = m_s[r];
                float mn = fmaxf(mo, rmax[i]);
                m_s[r]  = mn;
                sc_s[r] = __expf(mo - mn);
            }
        }
        __syncthreads();

        // P = exp(S - m), row sums, stash P in smem
        float rsum[4];
        #pragma unroll
        for (int i = 0; i < 4; ++i) {
            int r = ty*4+i;
            float mn = m_s[r];
            float s_ = 0.f;
            #pragma unroll
            for (int j = 0; j < 4; ++j) {
                float p = __expf(acc[i][j] - mn);
                Ps[r][tx*4+j] = p;
                s_ += p;
            }
            rsum[i] = s_;
        }
        #pragma unroll
        for (int s = 8; s; s >>= 1)
            #pragma unroll
            for (int i = 0; i < 4; ++i)
                rsum[i] += __shfl_xor_sync(0xffffffffu, rsum[i], s);
        if (tx == 0) {
            #pragma unroll
            for (int i = 0; i < 4; ++i) {
                int r = ty*4+i;
                l_s[r] = l_s[r]*sc_s[r] + rsum[i];
            }
        }
        __syncthreads();

        // rescale accumulators + O += P @ V
        #pragma unroll
        for (int i = 0; i < 4; ++i) {
            float sc = sc_s[ty*4+i];
            o[i][0] *= sc; o[i][1] *= sc;
        }
        #pragma unroll 4
        for (int m = 0; m < 64; ++m) {
            float v0 = Vs[m][tx*2], v1 = Vs[m][tx*2+1];
            #pragma unroll
            for (int i = 0; i < 4; ++i) {
                float p = Ps[ty*4+i][m];
                o[i][0] = fmaf(p, v0, o[i][0]);
                o[i][1] = fmaf(p, v1, o[i][1]);
            }
        }
        __syncthreads();
    }

    #pragma unroll
    for (int i = 0; i < 4; ++i) {
        int r = ty*4+i;
        float inv = 1.f / l_s[r];
        float* dst = g_attn + ((size_t)b*Ll + l0 + r)*Cc + n*HDd + tx*2;
        dst[0] = o[i][0]*inv;
        dst[1] = o[i][1]*inv;
    }
}

// ---------------------------------------------------------------------------
extern "C" void kernel_launch(void* const* d_in, const int* in_sizes, int n_in,
                              void* d_out, int out_size)
{
    const float* x    = (const float*)d_in[0];
    const float* sinp = (const float*)d_in[1];
    const float* cosp = (const float*)d_in[2];
    const float* mask = (const float*)d_in[3];
    const float* wq   = (const float*)d_in[4];
    const float* bq   = (const float*)d_in[5];
    const float* wk   = (const float*)d_in[6];
    const float* bk   = (const float*)d_in[7];
    const float* wv   = (const float*)d_in[8];
    const float* bv   = (const float*)d_in[9];
    const float* wdw  = (const float*)d_in[10];
    const float* bdw  = (const float*)d_in[11];
    const float* wo   = (const float*)d_in[12];
    const float* bo   = (const float*)d_in[13];

    float *pq, *pk, *pv, *pa, *pl;
    cudaGetSymbolAddress((void**)&pq, g_q);
    cudaGetSymbolAddress((void**)&pk, g_k);
    cudaGetSymbolAddress((void**)&pv, g_v);
    cudaGetSymbolAddress((void**)&pa, g_attn);
    cudaGetSymbolAddress((void**)&pl, g_lepe);

    dim3 gg(Rr/64, Cc/64);
    gemm_rope_kernel<<<gg, 256>>>(x, nullptr, wq, bq, sinp, cosp, pq, 0);
    gemm_rope_kernel<<<gg, 256>>>(x, nullptr, wk, bk, sinp, cosp, pk, 1);
    gemm_rope_kernel<<<gg, 256>>>(x, nullptr, wv, bv, sinp, cosp, pv, 2);

    lepe_kernel<<<(Rr*Cc + 255)/256, 256>>>(wdw, bdw);

    attn_kernel<<<dim3(Ll/64, Bb*NHh), 256>>>(mask);

    gemm_rope_kernel<<<gg, 256>>>(pa, pl, wo, bo, nullptr, nullptr, (float*)d_out, 2);
}

// round 2
// speedup vs baseline: 1.8634x; 1.8634x over previous
#include <cuda_runtime.h>
#include <math.h>

#define Bb 2
#define Hh 48
#define Ww 48
#define Cc 256
#define NHh 8
#define HDd 32
#define Ll 2304          // 48*48
#define Rr (Bb*Ll)       // 4608
#define SCALING 0.17677669529663687f  // 32^-0.5

// scratch (no cudaMalloc allowed)
__device__ float g_q[Rr*Cc];
__device__ float g_k[Rr*Cc];
__device__ float g_v[Rr*Cc];
__device__ float g_attn[Rr*Cc];
__device__ float g_lepe[Rr*Cc];

// ---------------------------------------------------------------------------
// tf32 helpers
// ---------------------------------------------------------------------------
__device__ __forceinline__ unsigned f2tf(float x) {
    unsigned u;
    asm("cvt.rna.tf32.f32 %0, %1;" : "=r"(u) : "f"(x));
    return u;
}

__device__ __forceinline__ void mma8(float4& c,
                                     unsigned a0, unsigned a1, unsigned a2, unsigned a3,
                                     unsigned b0, unsigned b1) {
    asm volatile(
        "mma.sync.aligned.m16n8k8.row.col.f32.tf32.tf32.f32 "
        "{%0,%1,%2,%3},{%4,%5,%6,%7},{%8,%9},{%0,%1,%2,%3};\n"
        : "+f"(c.x), "+f"(c.y), "+f"(c.z), "+f"(c.w)
        : "r"(a0), "r"(a1), "r"(a2), "r"(a3), "r"(b0), "r"(b1));
}

// ---------------------------------------------------------------------------
// GEMM: out[r,c] = (A[r,:] (+A2[r,:])) @ W[:,c] + bias[c]; optional RoPE epilogue.
// mode 0: rope (q) ; mode 1: scale then rope (k) ; mode 2: plain
// BM=64, BN=64, BK=16, 256 threads, 4x4 microtile.
// ---------------------------------------------------------------------------
__global__ __launch_bounds__(256) void gemm_rope_kernel(
    const float* __restrict__ A, const float* __restrict__ A2,
    const float* __restrict__ W, const float* __restrict__ bias,
    const float* __restrict__ sinp, const float* __restrict__ cosp,
    float* __restrict__ out, int mode)
{
    __shared__ float xs[64][16];
    __shared__ float ws[16][68];

    int tid = threadIdx.x;
    int tx = tid & 15, ty = tid >> 4;
    int row0 = blockIdx.x * 64;
    int col0 = blockIdx.y * 64;

    float acc[4][4] = {};

    for (int kt = 0; kt < Cc; kt += 16) {
        {
            int r = tid >> 2, kv = (tid & 3) * 4;
            float4 v4 = *reinterpret_cast<const float4*>(&A[(size_t)(row0 + r)*Cc + kt + kv]);
            if (A2) {
                float4 v2 = *reinterpret_cast<const float4*>(&A2[(size_t)(row0 + r)*Cc + kt + kv]);
                v4.x += v2.x; v4.y += v2.y; v4.z += v2.z; v4.w += v2.w;
            }
            *reinterpret_cast<float4*>(&xs[r][kv]) = v4;
        }
        {
            int kr = tid >> 4, cv = (tid & 15) * 4;
            float4 v4 = *reinterpret_cast<const float4*>(&W[(size_t)(kt + kr)*Cc + col0 + cv]);
            *reinterpret_cast<float4*>(&ws[kr][cv]) = v4;
        }
        __syncthreads();
        #pragma unroll
        for (int kk = 0; kk < 16; ++kk) {
            float a[4], b[4];
            #pragma unroll
            for (int i = 0; i < 4; ++i) a[i] = xs[ty*4+i][kk];
            #pragma unroll
            for (int j = 0; j < 4; ++j) b[j] = ws[kk][tx*4+j];
            #pragma unroll
            for (int i = 0; i < 4; ++i)
                #pragma unroll
                for (int j = 0; j < 4; ++j)
                    acc[i][j] = fmaf(a[i], b[j], acc[i][j]);
        }
        __syncthreads();
    }

    int colb = col0 + tx*4;
    float bi[4];
    #pragma unroll
    for (int j = 0; j < 4; ++j) bi[j] = bias[colb + j];

    #pragma unroll
    for (int i = 0; i < 4; ++i) {
        int rg = row0 + ty*4 + i;
        float v[4];
        #pragma unroll
        for (int j = 0; j < 4; ++j) v[j] = acc[i][j] + bi[j];
        if (mode == 1) {
            #pragma unroll
            for (int j = 0; j < 4; ++j) v[j] *= SCALING;
        }
        if (mode <= 1) {
            int l = rg % Ll;
            int h0 = colb & 31;
            const float* sb = sinp + (size_t)l*HDd + h0;
            const float* cb = cosp + (size_t)l*HDd + h0;
            float s0=sb[0], s1=sb[1], s2=sb[2], s3=sb[3];
            float c0=cb[0], c1=cb[1], c2=cb[2], c3=cb[3];
            float e0 = v[0]*c0 - v[1]*s0;
            float o0 = v[1]*c1 + v[0]*s1;
            float e1 = v[2]*c2 - v[3]*s2;
            float o1 = v[3]*c3 + v[2]*s3;
            v[0]=e0; v[1]=o0; v[2]=e1; v[3]=o1;
        }
        float4 st = make_float4(v[0], v[1], v[2], v[3]);
        *reinterpret_cast<float4*>(&out[(size_t)rg*Cc + colb]) = st;
    }
}

// ---------------------------------------------------------------------------
// Depthwise 5x5 conv (LEPE) on g_v -> g_lepe
// ---------------------------------------------------------------------------
__global__ __launch_bounds__(256) void lepe_kernel(
    const float* __restrict__ wdw, const float* __restrict__ bdw)
{
    int idx = blockIdx.x * blockDim.x + threadIdx.x;
    if (idx >= Rr*Cc) return;
    int c  = idx & (Cc-1);
    int rl = idx >> 8;
    int b  = rl / Ll;
    int l  = rl - b*Ll;
    int h  = l / Ww;
    int w  = l - h*Ww;

    float acc = bdw[c];
    #pragma unroll
    for (int kh = 0; kh < 5; ++kh) {
        int hh = h + kh - 2;
        if ((unsigned)hh >= (unsigned)Hh) continue;
        #pragma unroll
        for (int kw = 0; kw < 5; ++kw) {
            int ww2 = w + kw - 2;
            if ((unsigned)ww2 >= (unsigned)Ww) continue;
            acc = fmaf(g_v[((size_t)b*Ll + hh*Ww + ww2)*Cc + c],
                       wdw[(kh*5 + kw)*Cc + c], acc);
        }
    }
    g_lepe[idx] = acc;
}

// ---------------------------------------------------------------------------
// Flash attention, tf32 tensor cores (mma.sync.m16n8k8).
// 128 threads = 4 warps; 64 query rows/block (16/warp); KV tiles of 64.
// grid = (L/64, B*NH); y: n = y>>1, b = y&1 (mask L2 reuse across batch pair).
// ---------------------------------------------------------------------------
__global__ __launch_bounds__(128) void attn_tc_kernel(const float* __restrict__ mask)
{
    __shared__ float Ks[64][40];      // [key][hd], stride 40 -> conflict-free B frags
    __shared__ float Vs[64][40];
    __shared__ float Ps[4][16][68];   // per-warp P tile, stride 68 -> conflict-free A frags

    int tid  = threadIdx.x;
    int warp = tid >> 5, lane = tid & 31;
    int g = lane >> 2, t = lane & 3;
    int n = blockIdx.y >> 1, b = blockIdx.y & 1;
    int l0 = blockIdx.x * 64;
    int qrow = l0 + warp*16;

    const float* qb = g_q + ((size_t)(b*Ll + qrow))*Cc + n*HDd;
    const float* kb = g_k + ((size_t)b*Ll)*Cc + n*HDd;
    const float* vb = g_v + ((size_t)b*Ll)*Cc + n*HDd;
    const float* mb = mask + ((size_t)n*Ll + qrow)*Ll;

    // persistent Q fragments (tf32)
    unsigned qa[4][4];
    #pragma unroll
    for (int kc = 0; kc < 4; ++kc) {
        qa[kc][0] = f2tf(qb[(size_t)g*Cc     + kc*8 + t]);
        qa[kc][1] = f2tf(qb[(size_t)(g+8)*Cc + kc*8 + t]);
        qa[kc][2] = f2tf(qb[(size_t)g*Cc     + kc*8 + t + 4]);
        qa[kc][3] = f2tf(qb[(size_t)(g+8)*Cc + kc*8 + t + 4]);
    }

    float mA = -1e30f, mB = -1e30f, lA = 0.f, lB = 0.f;
    float4 o[4] = {};   // O frags: 4 n-blocks of HD=32

    for (int m0 = 0; m0 < Ll; m0 += 64) {
        // stage K,V tiles (converted to tf32 bit patterns)
        for (int j = tid; j < 512; j += 128) {
            int r = j >> 3, c4 = (j & 7)*4;
            float4 kv = *reinterpret_cast<const float4*>(&kb[(size_t)(m0+r)*Cc + c4]);
            Ks[r][c4+0] = __uint_as_float(f2tf(kv.x));
            Ks[r][c4+1] = __uint_as_float(f2tf(kv.y));
            Ks[r][c4+2] = __uint_as_float(f2tf(kv.z));
            Ks[r][c4+3] = __uint_as_float(f2tf(kv.w));
            float4 vv = *reinterpret_cast<const float4*>(&vb[(size_t)(m0+r)*Cc + c4]);
            Vs[r][c4+0] = __uint_as_float(f2tf(vv.x));
            Vs[r][c4+1] = __uint_as_float(f2tf(vv.y));
            Vs[r][c4+2] = __uint_as_float(f2tf(vv.z));
            Vs[r][c4+3] = __uint_as_float(f2tf(vv.w));
        }
        __syncthreads();

        // S = Q @ K^T  (16x64 per warp)
        float4 s[8];
        #pragma unroll
        for (int nb = 0; nb < 8; ++nb) {
            s[nb] = make_float4(0.f, 0.f, 0.f, 0.f);
            #pragma unroll
            for (int kc = 0; kc < 4; ++kc) {
                unsigned b0 = __float_as_uint(Ks[nb*8+g][kc*8+t]);
                unsigned b1 = __float_as_uint(Ks[nb*8+g][kc*8+t+4]);
                mma8(s[nb], qa[kc][0], qa[kc][1], qa[kc][2], qa[kc][3], b0, b1);
            }
        }

        // + mask, row-max (rows g and g+8 of this warp's 16)
        float mxA = -1e30f, mxB = -1e30f;
        #pragma unroll
        for (int nb = 0; nb < 8; ++nb) {
            float2 ma = *reinterpret_cast<const float2*>(&mb[(size_t)g*Ll     + m0 + nb*8 + 2*t]);
            float2 mc = *reinterpret_cast<const float2*>(&mb[(size_t)(g+8)*Ll + m0 + nb*8 + 2*t]);
            s[nb].x += ma.x; s[nb].y += ma.y;
            s[nb].z += mc.x; s[nb].w += mc.y;
            mxA = fmaxf(mxA, fmaxf(s[nb].x, s[nb].y));
            mxB = fmaxf(mxB, fmaxf(s[nb].z, s[nb].w));
        }
        mxA = fmaxf(mxA, __shfl_xor_sync(0xffffffffu, mxA, 1));
        mxA = fmaxf(mxA, __shfl_xor_sync(0xffffffffu, mxA, 2));
        mxB = fmaxf(mxB, __shfl_xor_sync(0xffffffffu, mxB, 1));
        mxB = fmaxf(mxB, __shfl_xor_sync(0xffffffffu, mxB, 2));

        float mAn = fmaxf(mA, mxA), mBn = fmaxf(mB, mxB);
        float scA = __expf(mA - mAn), scB = __expf(mB - mBn);
        mA = mAn; mB = mBn;

        // P = exp(S - m) -> smem (tf32); row sums
        float sA = 0.f, sB = 0.f;
        #pragma unroll
        for (int nb = 0; nb < 8; ++nb) {
            float p0 = __expf(s[nb].x - mA);
            float p1 = __expf(s[nb].y - mA);
            float p2 = __expf(s[nb].z - mB);
            float p3 = __expf(s[nb].w - mB);
            sA += p0 + p1; sB += p2 + p3;
            Ps[warp][g  ][nb*8 + 2*t    ] = __uint_as_float(f2tf(p0));
            Ps[warp][g  ][nb*8 + 2*t + 1] = __uint_as_float(f2tf(p1));
            Ps[warp][g+8][nb*8 + 2*t    ] = __uint_as_float(f2tf(p2));
            Ps[warp][g+8][nb*8 + 2*t + 1] = __uint_as_float(f2tf(p3));
        }
        sA += __shfl_xor_sync(0xffffffffu, sA, 1);
        sA += __shfl_xor_sync(0xffffffffu, sA, 2);
        sB += __shfl_xor_sync(0xffffffffu, sB, 1);
        sB += __shfl_xor_sync(0xffffffffu, sB, 2);
        lA = lA*scA + sA;
        lB = lB*scB + sB;

        // rescale O
        #pragma unroll
        for (int nv = 0; nv < 4; ++nv) {
            o[nv].x *= scA; o[nv].y *= scA;
            o[nv].z *= scB; o[nv].w *= scB;
        }
        __syncwarp();

        // O += P @ V   (16x32 per warp, K=64)
        #pragma unroll
        for (int kc = 0; kc < 8; ++kc) {
            unsigned a0 = __float_as_uint(Ps[warp][g  ][kc*8 + t    ]);
            unsigned a1 = __float_as_uint(Ps[warp][g+8][kc*8 + t    ]);
            unsigned a2 = __float_as_uint(Ps[warp][g  ][kc*8 + t + 4]);
            unsigned a3 = __float_as_uint(Ps[warp][g+8][kc*8 + t + 4]);
            #pragma unroll
            for (int nv = 0; nv < 4; ++nv) {
                unsigned b0 = __float_as_uint(Vs[kc*8 + t    ][nv*8 + g]);
                unsigned b1 = __float_as_uint(Vs[kc*8 + t + 4][nv*8 + g]);
                mma8(o[nv], a0, a1, a2, a3, b0, b1);
            }
        }
        __syncwarp();
        __syncthreads();
    }

    float invA = 1.f / lA, invB = 1.f / lB;
    float* ob = g_attn + ((size_t)(b*Ll + qrow))*Cc + n*HDd;
    #pragma unroll
    for (int nv = 0; nv < 4; ++nv) {
        float2 wA = make_float2(o[nv].x*invA, o[nv].y*invA);
        float2 wB = make_float2(o[nv].z*invB, o[nv].w*invB);
        *reinterpret_cast<float2*>(&ob[(size_t)g*Cc     + nv*8 + 2*t]) = wA;
        *reinterpret_cast<float2*>(&ob[(size_t)(g+8)*Cc + nv*8 + 2*t]) = wB;
    }
}

// ---------------------------------------------------------------------------
extern "C" void kernel_launch(void* const* d_in, const int* in_sizes, int n_in,
                              void* d_out, int out_size)
{
    const float* x    = (const float*)d_in[0];
    const float* sinp = (const float*)d_in[1];
    const float* cosp = (const float*)d_in[2];
    const float* mask = (const float*)d_in[3];
    const float* wq   = (const float*)d_in[4];
    const float* bq   = (const float*)d_in[5];
    const float* wk   = (const float*)d_in[6];
    const float* bk   = (const float*)d_in[7];
    const float* wv   = (const float*)d_in[8];
    const float* bv   = (const float*)d_in[9];
    const float* wdw  = (const float*)d_in[10];
    const float* bdw  = (const float*)d_in[11];
    const float* wo   = (const float*)d_in[12];
    const float* bo   = (const float*)d_in[13];

    float *pq, *pk, *pv, *pa, *pl;
    cudaGetSymbolAddress((void**)&pq, g_q);
    cudaGetSymbolAddress((void**)&pk, g_k);
    cudaGetSymbolAddress((void**)&pv, g_v);
    cudaGetSymbolAddress((void**)&pa, g_attn);
    cudaGetSymbolAddress((void**)&pl, g_lepe);

    dim3 gg(Rr/64, Cc/64);
    gemm_rope_kernel<<<gg, 256>>>(x, nullptr, wq, bq, sinp, cosp, pq, 0);
    gemm_rope_kernel<<<gg, 256>>>(x, nullptr, wk, bk, sinp, cosp, pk, 1);
    gemm_rope_kernel<<<gg, 256>>>(x, nullptr, wv, bv, sinp, cosp, pv, 2);

    lepe_kernel<<<(Rr*Cc + 255)/256, 256>>>(wdw, bdw);

    attn_tc_kernel<<<dim3(Ll/64, Bb*NHh), 128>>>(mask);

    gemm_rope_kernel<<<gg, 256>>>(pa, pl, wo, bo, nullptr, nullptr, (float*)d_out, 2);
}

// round 5
// speedup vs baseline: 2.1659x; 1.1623x over previous
#include <cuda_runtime.h>
#include <math.h>

#define Bb 2
#define Hh 48
#define Ww 48
#define Cc 256
#define NHh 8
#define HDd 32
#define Ll 2304          // 48*48
#define Rr (Bb*Ll)       // 4608
#define SCALING 0.17677669529663687f  // 32^-0.5

// scratch (no cudaMalloc allowed)
__device__ float g_q[Rr*Cc];
__device__ float g_k[Rr*Cc];
__device__ float g_v[Rr*Cc];
__device__ float g_attn[Rr*Cc];
__device__ float g_lepe[Rr*Cc];

// ---------------------------------------------------------------------------
// helpers
// ---------------------------------------------------------------------------
__device__ __forceinline__ unsigned f2tf(float x) {
    unsigned u;
    asm("cvt.rna.tf32.f32 %0, %1;" : "=r"(u) : "f"(x));
    return u;
}
__device__ __forceinline__ float f2tff(float x) {
    return __uint_as_float(f2tf(x));
}

__device__ __forceinline__ void mma8(float4& c,
                                     unsigned a0, unsigned a1, unsigned a2, unsigned a3,
                                     unsigned b0, unsigned b1) {
    asm volatile(
        "mma.sync.aligned.m16n8k8.row.col.f32.tf32.tf32.f32 "
        "{%0,%1,%2,%3},{%4,%5,%6,%7},{%8,%9},{%0,%1,%2,%3};\n"
        : "+f"(c.x), "+f"(c.y), "+f"(c.z), "+f"(c.w)
        : "r"(a0), "r"(a1), "r"(a2), "r"(a3), "r"(b0), "r"(b1));
}

__device__ __forceinline__ void cpa16(void* dst, const void* src) {
    unsigned d = (unsigned)__cvta_generic_to_shared(dst);
    asm volatile("cp.async.ca.shared.global [%0], [%1], 16;\n" :: "r"(d), "l"(src));
}
#define CP_COMMIT() asm volatile("cp.async.commit_group;\n" ::: "memory")
#define CP_WAIT1()  asm volatile("cp.async.wait_group 1;\n" ::: "memory")

// ---------------------------------------------------------------------------
// tf32 tensor-core GEMM: out = (A (+A2)) @ W + bias, optional RoPE epilogue.
// mode 0: rope (q); 1: scale+rope (k); 2: plain.
// 64x64 block, BK=32, 4 warps (2x2 of 32x32 warp tiles), m16n8k8.
// A/B tiles RNA-rounded to tf32 during staging (unbiased).
// ---------------------------------------------------------------------------
__global__ __launch_bounds__(128) void gemm_tc_kernel(
    const float* __restrict__ A, const float* __restrict__ A2,
    const float* __restrict__ W, const float* __restrict__ bias,
    const float* __restrict__ sinp, const float* __restrict__ cosp,
    float* __restrict__ out, int mode)
{
    __shared__ float As[64][36];   // bank(4g+t): A-frag reads conflict-free
    __shared__ float Bs[32][72];   // 32 x 64 tile + pad 8: bank(8t+g) conflict-free

    int tid = threadIdx.x;
    int warp = tid >> 5, lane = tid & 31;
    int g = lane >> 2, t = lane & 3;
    int wm = warp >> 1, wn = warp & 1;
    int row0 = blockIdx.x * 64;
    int col0 = blockIdx.y * 64;

    float4 c[2][4];
    #pragma unroll
    for (int i = 0; i < 2; ++i)
        #pragma unroll
        for (int j = 0; j < 4; ++j) c[i][j] = make_float4(0.f,0.f,0.f,0.f);

    for (int kt = 0; kt < Cc; kt += 32) {
        // stage A: 64x32, RNA -> tf32
        {
            int r = tid >> 3, c4 = (tid & 7) * 4;   // r 0..15
            #pragma unroll
            for (int rr = 0; rr < 64; rr += 16) {
                float4 v = *reinterpret_cast<const float4*>(&A[(size_t)(row0+r+rr)*Cc + kt + c4]);
                if (A2) {
                    float4 v2 = *reinterpret_cast<const float4*>(&A2[(size_t)(row0+r+rr)*Cc + kt + c4]);
                    v.x += v2.x; v.y += v2.y; v.z += v2.z; v.w += v2.w;
                }
                v.x = f2tff(v.x); v.y = f2tff(v.y); v.z = f2tff(v.z); v.w = f2tff(v.w);
                *reinterpret_cast<float4*>(&As[r+rr][c4]) = v;
            }
        }
        // stage B: 32x64 (k-major rows of W), RNA -> tf32
        {
            int kr = tid >> 4, cv = (tid & 15) * 4; // kr 0..7, cv 0..60
            #pragma unroll
            for (int kk = 0; kk < 32; kk += 8) {
                float4 v = *reinterpret_cast<const float4*>(&W[(size_t)(kt+kr+kk)*Cc + col0 + cv]);
                v.x = f2tff(v.x); v.y = f2tff(v.y); v.z = f2tff(v.z); v.w = f2tff(v.w);
                *reinterpret_cast<float4*>(&Bs[kr+kk][cv]) = v;
            }
        }
        __syncthreads();

        #pragma unroll
        for (int kc = 0; kc < 4; ++kc) {
            unsigned a[2][4];
            #pragma unroll
            for (int i = 0; i < 2; ++i) {
                int rbase = wm*32 + i*16;
                a[i][0] = __float_as_uint(As[rbase+g  ][kc*8+t  ]);
                a[i][1] = __float_as_uint(As[rbase+g+8][kc*8+t  ]);
                a[i][2] = __float_as_uint(As[rbase+g  ][kc*8+t+4]);
                a[i][3] = __float_as_uint(As[rbase+g+8][kc*8+t+4]);
            }
            #pragma unroll
            for (int j = 0; j < 4; ++j) {
                unsigned b0 = __float_as_uint(Bs[kc*8+t  ][wn*32 + j*8 + g]);
                unsigned b1 = __float_as_uint(Bs[kc*8+t+4][wn*32 + j*8 + g]);
                #pragma unroll
                for (int i = 0; i < 2; ++i)
                    mma8(c[i][j], a[i][0], a[i][1], a[i][2], a[i][3], b0, b1);
            }
        }
        __syncthreads();
    }

    // epilogue
    #pragma unroll
    for (int j = 0; j < 4; ++j) {
        int cb = col0 + wn*32 + j*8 + 2*t;
        float2 bi = *reinterpret_cast<const float2*>(&bias[cb]);
        #pragma unroll
        for (int i = 0; i < 2; ++i) {
            int r0 = row0 + wm*32 + i*16 + g;
            int r1 = r0 + 8;
            float v0 = c[i][j].x + bi.x, v1 = c[i][j].y + bi.y;   // row r0
            float w0 = c[i][j].z + bi.x, w1 = c[i][j].w + bi.y;   // row r1
            if (mode == 1) { v0*=SCALING; v1*=SCALING; w0*=SCALING; w1*=SCALING; }
            if (mode <= 1) {
                int hd = cb & 31;
                int l0 = (r0 >= Ll) ? r0 - Ll : r0;
                int l1 = (r1 >= Ll) ? r1 - Ll : r1;
                float2 s0 = *reinterpret_cast<const float2*>(&sinp[(size_t)l0*HDd + hd]);
                float2 c0 = *reinterpret_cast<const float2*>(&cosp[(size_t)l0*HDd + hd]);
                float2 s1 = *reinterpret_cast<const float2*>(&sinp[(size_t)l1*HDd + hd]);
                float2 c1 = *reinterpret_cast<const float2*>(&cosp[(size_t)l1*HDd + hd]);
                float e0 = v0*c0.x - v1*s0.x;
                float o0 = v1*c0.y + v0*s0.y;
                float e1 = w0*c1.x - w1*s1.x;
                float o1 = w1*c1.y + w0*s1.y;
                v0=e0; v1=o0; w0=e1; w1=o1;
            }
            *reinterpret_cast<float2*>(&out[(size_t)r0*Cc + cb]) = make_float2(v0, v1);
            *reinterpret_cast<float2*>(&out[(size_t)r1*Cc + cb]) = make_float2(w0, w1);
        }
    }
}

// ---------------------------------------------------------------------------
// Depthwise 5x5 conv (LEPE): grid (Ll, Bb), block 256 (= channels)
// ---------------------------------------------------------------------------
__global__ __launch_bounds__(256) void lepe_kernel(
    const float* __restrict__ wdw, const float* __restrict__ bdw)
{
    int c = threadIdx.x;
    int l = blockIdx.x;
    int b = blockIdx.y;
    int h = l / Ww;
    int w = l - h*Ww;

    float acc = bdw[c];
    #pragma unroll
    for (int kh = 0; kh < 5; ++kh) {
        int hh = h + kh - 2;
        if ((unsigned)hh >= (unsigned)Hh) continue;
        #pragma unroll
        for (int kw = 0; kw < 5; ++kw) {
            int ww2 = w + kw - 2;
            if ((unsigned)ww2 >= (unsigned)Ww) continue;
            acc = fmaf(g_v[((size_t)b*Ll + hh*Ww + ww2)*Cc + c],
                       wdw[(kh*5 + kw)*Cc + c], acc);
        }
    }
    g_lepe[((size_t)b*Ll + l)*Cc + c] = acc;
}

// ---------------------------------------------------------------------------
// Flash attention, tf32 tensor cores, cp.async double-buffered K/V with
// in-place RNA conversion (each thread converts exactly what it staged).
// 256 threads = 8 warps; 128 Q rows/block (16/warp); KV tiles of 64.
// grid = (Ll/128, B*NH); y: n = y>>1, b = y&1.
// dynamic smem: Ks[2][64][36] | Vs[2][64][40] | Ps[8][16][68]
// ---------------------------------------------------------------------------
#define KS_OFF 0
#define VS_OFF (2*64*36)
#define PS_OFF (VS_OFF + 2*64*40)
#define SMEM_FLOATS (PS_OFF + 8*16*68)

__device__ __forceinline__ void cvt_inplace4(float* p) {
    float4 v = *reinterpret_cast<float4*>(p);
    v.x = f2tff(v.x); v.y = f2tff(v.y); v.z = f2tff(v.z); v.w = f2tff(v.w);
    *reinterpret_cast<float4*>(p) = v;
}

__global__ __launch_bounds__(256, 2) void attn_tc_kernel(const float* __restrict__ mask)
{
    extern __shared__ float sm[];
    float (*Ks)[64][36] = reinterpret_cast<float(*)[64][36]>(sm + KS_OFF);
    float (*Vs)[64][40] = reinterpret_cast<float(*)[64][40]>(sm + VS_OFF);
    float (*Ps)[16][68] = reinterpret_cast<float(*)[16][68]>(sm + PS_OFF);

    int tid  = threadIdx.x;
    int warp = tid >> 5, lane = tid & 31;
    int g = lane >> 2, t = lane & 3;
    int n = blockIdx.y >> 1, b = blockIdx.y & 1;
    int l0 = blockIdx.x * 128;
    int qrow = l0 + warp*16;

    const float* qb = g_q + ((size_t)(b*Ll + qrow))*Cc + n*HDd;
    const float* kb = g_k + ((size_t)b*Ll)*Cc + n*HDd;
    const float* vb = g_v + ((size_t)b*Ll)*Cc + n*HDd;
    const float* mb = mask + ((size_t)n*Ll + qrow)*Ll;

    // persistent Q fragments (RNA tf32)
    unsigned qa[4][4];
    #pragma unroll
    for (int kc = 0; kc < 4; ++kc) {
        qa[kc][0] = f2tf(qb[(size_t)g*Cc     + kc*8 + t]);
        qa[kc][1] = f2tf(qb[(size_t)(g+8)*Cc + kc*8 + t]);
        qa[kc][2] = f2tf(qb[(size_t)g*Cc     + kc*8 + t + 4]);
        qa[kc][3] = f2tf(qb[(size_t)(g+8)*Cc + kc*8 + t + 4]);
    }

    // staging coords: 4 cp.async of 16B per thread per tile
    int sr = tid >> 3;            // 0..31
    int sc = (tid & 7) * 4;

    // prologue: tile 0 -> buf 0
    cpa16(&Ks[0][sr   ][sc], &kb[(size_t)(sr   )*Cc + sc]);
    cpa16(&Ks[0][sr+32][sc], &kb[(size_t)(sr+32)*Cc + sc]);
    cpa16(&Vs[0][sr   ][sc], &vb[(size_t)(sr   )*Cc + sc]);
    cpa16(&Vs[0][sr+32][sc], &vb[(size_t)(sr+32)*Cc + sc]);
    CP_COMMIT();

    float mA = -1e30f, mB = -1e30f, lA = 0.f, lB = 0.f;
    float4 o[4] = {};

    for (int tile = 0; tile < Ll/64; ++tile) {
        int buf = tile & 1;
        int m0 = tile * 64;
        if (m0 + 64 < Ll) {
            int nb0 = m0 + 64, ob = buf ^ 1;
            cpa16(&Ks[ob][sr   ][sc], &kb[(size_t)(nb0+sr   )*Cc + sc]);
            cpa16(&Ks[ob][sr+32][sc], &kb[(size_t)(nb0+sr+32)*Cc + sc]);
            cpa16(&Vs[ob][sr   ][sc], &vb[(size_t)(nb0+sr   )*Cc + sc]);
            cpa16(&Vs[ob][sr+32][sc], &vb[(size_t)(nb0+sr+32)*Cc + sc]);
        }
        CP_COMMIT();
        CP_WAIT1();
        // convert own staged regions to RNA tf32 (own cp.asyncs are complete)
        cvt_inplace4(&Ks[buf][sr   ][sc]);
        cvt_inplace4(&Ks[buf][sr+32][sc]);
        cvt_inplace4(&Vs[buf][sr   ][sc]);
        cvt_inplace4(&Vs[buf][sr+32][sc]);
        __syncthreads();

        // S = Q @ K^T  (16x64 per warp)
        float4 s[8];
        #pragma unroll
        for (int nb = 0; nb < 8; ++nb) {
            s[nb] = make_float4(0.f, 0.f, 0.f, 0.f);
            #pragma unroll
            for (int kc = 0; kc < 4; ++kc) {
                unsigned b0 = __float_as_uint(Ks[buf][nb*8+g][kc*8+t]);
                unsigned b1 = __float_as_uint(Ks[buf][nb*8+g][kc*8+t+4]);
                mma8(s[nb], qa[kc][0], qa[kc][1], qa[kc][2], qa[kc][3], b0, b1);
            }
        }

        // + mask, row-max
        float mxA = -1e30f, mxB = -1e30f;
        #pragma unroll
        for (int nb = 0; nb < 8; ++nb) {
            float2 ma = *reinterpret_cast<const float2*>(&mb[(size_t)g*Ll     + m0 + nb*8 + 2*t]);
            float2 mc = *reinterpret_cast<const float2*>(&mb[(size_t)(g+8)*Ll + m0 + nb*8 + 2*t]);
            s[nb].x += ma.x; s[nb].y += ma.y;
            s[nb].z += mc.x; s[nb].w += mc.y;
            mxA = fmaxf(mxA, fmaxf(s[nb].x, s[nb].y));
            mxB = fmaxf(mxB, fmaxf(s[nb].z, s[nb].w));
        }
        mxA = fmaxf(mxA, __shfl_xor_sync(0xffffffffu, mxA, 1));
        mxA = fmaxf(mxA, __shfl_xor_sync(0xffffffffu, mxA, 2));
        mxB = fmaxf(mxB, __shfl_xor_sync(0xffffffffu, mxB, 1));
        mxB = fmaxf(mxB, __shfl_xor_sync(0xffffffffu, mxB, 2));

        float mAn = fmaxf(mA, mxA), mBn = fmaxf(mB, mxB);
        float scA = __expf(mA - mAn), scB = __expf(mB - mBn);
        mA = mAn; mB = mBn;

        // P = exp(S - m) -> smem (RNA tf32); row sums in fp32
        float sA = 0.f, sB = 0.f;
        #pragma unroll
        for (int nb = 0; nb < 8; ++nb) {
            float p0 = __expf(s[nb].x - mA);
            float p1 = __expf(s[nb].y - mA);
            float p2 = __expf(s[nb].z - mB);
            float p3 = __expf(s[nb].w - mB);
            sA += p0 + p1; sB += p2 + p3;
            Ps[warp][g  ][nb*8 + 2*t    ] = __uint_as_float(f2tf(p0));
            Ps[warp][g  ][nb*8 + 2*t + 1] = __uint_as_float(f2tf(p1));
            Ps[warp][g+8][nb*8 + 2*t    ] = __uint_as_float(f2tf(p2));
            Ps[warp][g+8][nb*8 + 2*t + 1] = __uint_as_float(f2tf(p3));
        }
        sA += __shfl_xor_sync(0xffffffffu, sA, 1);
        sA += __shfl_xor_sync(0xffffffffu, sA, 2);
        sB += __shfl_xor_sync(0xffffffffu, sB, 1);
        sB += __shfl_xor_sync(0xffffffffu, sB, 2);
        lA = lA*scA + sA;
        lB = lB*scB + sB;

        // rescale O
        #pragma unroll
        for (int nv = 0; nv < 4; ++nv) {
            o[nv].x *= scA; o[nv].y *= scA;
            o[nv].z *= scB; o[nv].w *= scB;
        }
        __syncwarp();

        // O += P @ V
        #pragma unroll
        for (int kc = 0; kc < 8; ++kc) {
            unsigned a0 = __float_as_uint(Ps[warp][g  ][kc*8 + t    ]);
            unsigned a1 = __float_as_uint(Ps[warp][g+8][kc*8 + t    ]);
            unsigned a2 = __float_as_uint(Ps[warp][g  ][kc*8 + t + 4]);
            unsigned a3 = __float_as_uint(Ps[warp][g+8][kc*8 + t + 4]);
            #pragma unroll
            for (int nv = 0; nv < 4; ++nv) {
                unsigned b0 = __float_as_uint(Vs[buf][kc*8 + t    ][nv*8 + g]);
                unsigned b1 = __float_as_uint(Vs[buf][kc*8 + t + 4][nv*8 + g]);
                mma8(o[nv], a0, a1, a2, a3, b0, b1);
            }
        }
        __syncthreads();   // everyone done with buf before it's overwritten next iter
    }

    float invA = 1.f / lA, invB = 1.f / lB;
    float* ob = g_attn + ((size_t)(b*Ll + qrow))*Cc + n*HDd;
    #pragma unroll
    for (int nv = 0; nv < 4; ++nv) {
        float2 wA = make_float2(o[nv].x*invA, o[nv].y*invA);
        float2 wB = make_float2(o[nv].z*invB, o[nv].w*invB);
        *reinterpret_cast<float2*>(&ob[(size_t)g*Cc     + nv*8 + 2*t]) = wA;
        *reinterpret_cast<float2*>(&ob[(size_t)(g+8)*Cc + nv*8 + 2*t]) = wB;
    }
}

// ---------------------------------------------------------------------------
extern "C" void kernel_launch(void* const* d_in, const int* in_sizes, int n_in,
                              void* d_out, int out_size)
{
    const float* x    = (const float*)d_in[0];
    const float* sinp = (const float*)d_in[1];
    const float* cosp = (const float*)d_in[2];
    const float* mask = (const float*)d_in[3];
    const float* wq   = (const float*)d_in[4];
    const float* bq   = (const float*)d_in[5];
    const float* wk   = (const float*)d_in[6];
    const float* bk   = (const float*)d_in[7];
    const float* wv   = (const float*)d_in[8];
    const float* bv   = (const float*)d_in[9];
    const float* wdw  = (const float*)d_in[10];
    const float* bdw  = (const float*)d_in[11];
    const float* wo   = (const float*)d_in[12];
    const float* bo   = (const float*)d_in[13];

    float *pq, *pk, *pv, *pa, *pl;
    cudaGetSymbolAddress((void**)&pq, g_q);
    cudaGetSymbolAddress((void**)&pk, g_k);
    cudaGetSymbolAddress((void**)&pv, g_v);
    cudaGetSymbolAddress((void**)&pa, g_attn);
    cudaGetSymbolAddress((void**)&pl, g_lepe);

    cudaFuncSetAttribute(attn_tc_kernel,
                         cudaFuncAttributeMaxDynamicSharedMemorySize,
                         SMEM_FLOATS * (int)sizeof(float));

    dim3 gg(Rr/64, Cc/64);
    gemm_tc_kernel<<<gg, 128>>>(x, nullptr, wq, bq, sinp, cosp, pq, 0);
    gemm_tc_kernel<<<gg, 128>>>(x, nullptr, wk, bk, sinp, cosp, pk, 1);
    gemm_tc_kernel<<<gg, 128>>>(x, nullptr, wv, bv, sinp, cosp, pv, 2);

    lepe_kernel<<<dim3(Ll, Bb), 256>>>(wdw, bdw);

    attn_tc_kernel<<<dim3(Ll/128, Bb*NHh), 256, SMEM_FLOATS*sizeof(float)>>>(mask);

    gemm_tc_kernel<<<gg, 128>>>(pa, pl, wo, bo, nullptr, nullptr, (float*)d_out, 2);
}

// round 6
// speedup vs baseline: 2.5024x; 1.1554x over previous
#include <cuda_runtime.h>
#include <math.h>

#define Bb 2
#define Hh 48
#define Ww 48
#define Cc 256
#define NHh 8
#define HDd 32
#define Ll 2304          // 48*48
#define Rr (Bb*Ll)       // 4608
#define SCALING 0.17677669529663687f  // 32^-0.5

// scratch (no cudaMalloc allowed)
__device__ float g_q[Rr*Cc];
__device__ float g_k[Rr*Cc];
__device__ float g_v[Rr*Cc];
__device__ float g_attn[Rr*Cc];
__device__ float g_lepe[Rr*Cc];

// ---------------------------------------------------------------------------
// helpers
// ---------------------------------------------------------------------------
__device__ __forceinline__ unsigned f2tf(float x) {
    unsigned u;
    asm("cvt.rna.tf32.f32 %0, %1;" : "=r"(u) : "f"(x));
    return u;
}
__device__ __forceinline__ float f2tff(float x) {
    return __uint_as_float(f2tf(x));
}

__device__ __forceinline__ void mma8(float4& c,
                                     unsigned a0, unsigned a1, unsigned a2, unsigned a3,
                                     unsigned b0, unsigned b1) {
    asm volatile(
        "mma.sync.aligned.m16n8k8.row.col.f32.tf32.tf32.f32 "
        "{%0,%1,%2,%3},{%4,%5,%6,%7},{%8,%9},{%0,%1,%2,%3};\n"
        : "+f"(c.x), "+f"(c.y), "+f"(c.z), "+f"(c.w)
        : "r"(a0), "r"(a1), "r"(a2), "r"(a3), "r"(b0), "r"(b1));
}

__device__ __forceinline__ void cpa16(void* dst, const void* src) {
    unsigned d = (unsigned)__cvta_generic_to_shared(dst);
    asm volatile("cp.async.ca.shared.global [%0], [%1], 16;\n" :: "r"(d), "l"(src));
}
#define CP_COMMIT() asm volatile("cp.async.commit_group;\n" ::: "memory")
#define CP_WAIT1()  asm volatile("cp.async.wait_group 1;\n" ::: "memory")
#define CP_WAIT2()  asm volatile("cp.async.wait_group 2;\n" ::: "memory")

// ---------------------------------------------------------------------------
// Fused QKV tf32 GEMM: q/k/v = x @ {wq,wk,wv} + bias, RoPE on q, scale+RoPE on k.
// 64x64 block, BK=32, 4 warps (2x2 of 32x32 warp tiles), m16n8k8.
// ---------------------------------------------------------------------------
__global__ __launch_bounds__(128) void qkv_tc_kernel(
    const float* __restrict__ x,
    const float* __restrict__ wq, const float* __restrict__ bq,
    const float* __restrict__ wk, const float* __restrict__ bk,
    const float* __restrict__ wv, const float* __restrict__ bv,
    const float* __restrict__ sinp, const float* __restrict__ cosp)
{
    __shared__ float As[64][36];      // bank(4g+t) conflict-free
    __shared__ float Bs[3][32][72];   // bank(8t+g) conflict-free

    int tid = threadIdx.x;
    int warp = tid >> 5, lane = tid & 31;
    int g = lane >> 2, t = lane & 3;
    int wm = warp >> 1, wn = warp & 1;
    int row0 = blockIdx.x * 64;
    int col0 = blockIdx.y * 64;

    const float* Wm[3] = { wq, wk, wv };

    float4 c[3][2][4];
    #pragma unroll
    for (int m = 0; m < 3; ++m)
        #pragma unroll
        for (int i = 0; i < 2; ++i)
            #pragma unroll
            for (int j = 0; j < 4; ++j) c[m][i][j] = make_float4(0.f,0.f,0.f,0.f);

    for (int kt = 0; kt < Cc; kt += 32) {
        // stage A (x tile): 64x32, RNA -> tf32
        {
            int r = tid >> 3, c4 = (tid & 7) * 4;
            #pragma unroll
            for (int rr = 0; rr < 64; rr += 16) {
                float4 v = *reinterpret_cast<const float4*>(&x[(size_t)(row0+r+rr)*Cc + kt + c4]);
                v.x = f2tff(v.x); v.y = f2tff(v.y); v.z = f2tff(v.z); v.w = f2tff(v.w);
                *reinterpret_cast<float4*>(&As[r+rr][c4]) = v;
            }
        }
        // stage 3 B tiles: 32x64 each, RNA -> tf32
        {
            int kr = tid >> 4, cv = (tid & 15) * 4;
            #pragma unroll
            for (int m = 0; m < 3; ++m) {
                const float* W = Wm[m];
                #pragma unroll
                for (int kk = 0; kk < 32; kk += 8) {
                    float4 v = *reinterpret_cast<const float4*>(&W[(size_t)(kt+kr+kk)*Cc + col0 + cv]);
                    v.x = f2tff(v.x); v.y = f2tff(v.y); v.z = f2tff(v.z); v.w = f2tff(v.w);
                    *reinterpret_cast<float4*>(&Bs[m][kr+kk][cv]) = v;
                }
            }
        }
        __syncthreads();

        #pragma unroll
        for (int kc = 0; kc < 4; ++kc) {
            unsigned a[2][4];
            #pragma unroll
            for (int i = 0; i < 2; ++i) {
                int rbase = wm*32 + i*16;
                a[i][0] = __float_as_uint(As[rbase+g  ][kc*8+t  ]);
                a[i][1] = __float_as_uint(As[rbase+g+8][kc*8+t  ]);
                a[i][2] = __float_as_uint(As[rbase+g  ][kc*8+t+4]);
                a[i][3] = __float_as_uint(As[rbase+g+8][kc*8+t+4]);
            }
            #pragma unroll
            for (int j = 0; j < 4; ++j) {
                #pragma unroll
                for (int m = 0; m < 3; ++m) {
                    unsigned b0 = __float_as_uint(Bs[m][kc*8+t  ][wn*32 + j*8 + g]);
                    unsigned b1 = __float_as_uint(Bs[m][kc*8+t+4][wn*32 + j*8 + g]);
                    #pragma unroll
                    for (int i = 0; i < 2; ++i)
                        mma8(c[m][i][j], a[i][0], a[i][1], a[i][2], a[i][3], b0, b1);
                }
            }
        }
        __syncthreads();
    }

    // epilogue: q (rope), k (scale+rope), v (plain)
    #pragma unroll
    for (int j = 0; j < 4; ++j) {
        int cb = col0 + wn*32 + j*8 + 2*t;
        int hd = cb & 31;
        float2 biq = *reinterpret_cast<const float2*>(&bq[cb]);
        float2 bik = *reinterpret_cast<const float2*>(&bk[cb]);
        float2 biv = *reinterpret_cast<const float2*>(&bv[cb]);
        #pragma unroll
        for (int i = 0; i < 2; ++i) {
            int r0 = row0 + wm*32 + i*16 + g;
            int r1 = r0 + 8;
            int l0 = (r0 >= Ll) ? r0 - Ll : r0;
            int l1 = (r1 >= Ll) ? r1 - Ll : r1;
            float2 s0 = *reinterpret_cast<const float2*>(&sinp[(size_t)l0*HDd + hd]);
            float2 c0 = *reinterpret_cast<const float2*>(&cosp[(size_t)l0*HDd + hd]);
            float2 s1 = *reinterpret_cast<const float2*>(&sinp[(size_t)l1*HDd + hd]);
            float2 c1 = *reinterpret_cast<const float2*>(&cosp[(size_t)l1*HDd + hd]);

            // q: rope
            {
                float v0 = c[0][i][j].x + biq.x, v1 = c[0][i][j].y + biq.y;
                float w0 = c[0][i][j].z + biq.x, w1 = c[0][i][j].w + biq.y;
                float e0 = v0*c0.x - v1*s0.x, o0 = v1*c0.y + v0*s0.y;
                float e1 = w0*c1.x - w1*s1.x, o1 = w1*c1.y + w0*s1.y;
                *reinterpret_cast<float2*>(&g_q[(size_t)r0*Cc + cb]) = make_float2(e0, o0);
                *reinterpret_cast<float2*>(&g_q[(size_t)r1*Cc + cb]) = make_float2(e1, o1);
            }
            // k: scale + rope
            {
                float v0 = (c[1][i][j].x + bik.x)*SCALING, v1 = (c[1][i][j].y + bik.y)*SCALING;
                float w0 = (c[1][i][j].z + bik.x)*SCALING, w1 = (c[1][i][j].w + bik.y)*SCALING;
                float e0 = v0*c0.x - v1*s0.x, o0 = v1*c0.y + v0*s0.y;
                float e1 = w0*c1.x - w1*s1.x, o1 = w1*c1.y + w0*s1.y;
                *reinterpret_cast<float2*>(&g_k[(size_t)r0*Cc + cb]) = make_float2(e0, o0);
                *reinterpret_cast<float2*>(&g_k[(size_t)r1*Cc + cb]) = make_float2(e1, o1);
            }
            // v: plain
            {
                float v0 = c[2][i][j].x + biv.x, v1 = c[2][i][j].y + biv.y;
                float w0 = c[2][i][j].z + biv.x, w1 = c[2][i][j].w + biv.y;
                *reinterpret_cast<float2*>(&g_v[(size_t)r0*Cc + cb]) = make_float2(v0, v1);
                *reinterpret_cast<float2*>(&g_v[(size_t)r1*Cc + cb]) = make_float2(w0, w1);
            }
        }
    }
}

// ---------------------------------------------------------------------------
// tf32 tensor-core GEMM (out-projection): out = (A + A2) @ W + bias.
// ---------------------------------------------------------------------------
__global__ __launch_bounds__(128) void gemm_tc_kernel(
    const float* __restrict__ A, const float* __restrict__ A2,
    const float* __restrict__ W, const float* __restrict__ bias,
    float* __restrict__ out)
{
    __shared__ float As[64][36];
    __shared__ float Bs[32][72];

    int tid = threadIdx.x;
    int warp = tid >> 5, lane = tid & 31;
    int g = lane >> 2, t = lane & 3;
    int wm = warp >> 1, wn = warp & 1;
    int row0 = blockIdx.x * 64;
    int col0 = blockIdx.y * 64;

    float4 c[2][4];
    #pragma unroll
    for (int i = 0; i < 2; ++i)
        #pragma unroll
        for (int j = 0; j < 4; ++j) c[i][j] = make_float4(0.f,0.f,0.f,0.f);

    for (int kt = 0; kt < Cc; kt += 32) {
        {
            int r = tid >> 3, c4 = (tid & 7) * 4;
            #pragma unroll
            for (int rr = 0; rr < 64; rr += 16) {
                float4 v = *reinterpret_cast<const float4*>(&A[(size_t)(row0+r+rr)*Cc + kt + c4]);
                float4 v2 = *reinterpret_cast<const float4*>(&A2[(size_t)(row0+r+rr)*Cc + kt + c4]);
                v.x = f2tff(v.x + v2.x); v.y = f2tff(v.y + v2.y);
                v.z = f2tff(v.z + v2.z); v.w = f2tff(v.w + v2.w);
                *reinterpret_cast<float4*>(&As[r+rr][c4]) = v;
            }
        }
        {
            int kr = tid >> 4, cv = (tid & 15) * 4;
            #pragma unroll
            for (int kk = 0; kk < 32; kk += 8) {
                float4 v = *reinterpret_cast<const float4*>(&W[(size_t)(kt+kr+kk)*Cc + col0 + cv]);
                v.x = f2tff(v.x); v.y = f2tff(v.y); v.z = f2tff(v.z); v.w = f2tff(v.w);
                *reinterpret_cast<float4*>(&Bs[kr+kk][cv]) = v;
            }
        }
        __syncthreads();

        #pragma unroll
        for (int kc = 0; kc < 4; ++kc) {
            unsigned a[2][4];
            #pragma unroll
            for (int i = 0; i < 2; ++i) {
                int rbase = wm*32 + i*16;
                a[i][0] = __float_as_uint(As[rbase+g  ][kc*8+t  ]);
                a[i][1] = __float_as_uint(As[rbase+g+8][kc*8+t  ]);
                a[i][2] = __float_as_uint(As[rbase+g  ][kc*8+t+4]);
                a[i][3] = __float_as_uint(As[rbase+g+8][kc*8+t+4]);
            }
            #pragma unroll
            for (int j = 0; j < 4; ++j) {
                unsigned b0 = __float_as_uint(Bs[kc*8+t  ][wn*32 + j*8 + g]);
                unsigned b1 = __float_as_uint(Bs[kc*8+t+4][wn*32 + j*8 + g]);
                #pragma unroll
                for (int i = 0; i < 2; ++i)
                    mma8(c[i][j], a[i][0], a[i][1], a[i][2], a[i][3], b0, b1);
            }
        }
        __syncthreads();
    }

    #pragma unroll
    for (int j = 0; j < 4; ++j) {
        int cb = col0 + wn*32 + j*8 + 2*t;
        float2 bi = *reinterpret_cast<const float2*>(&bias[cb]);
        #pragma unroll
        for (int i = 0; i < 2; ++i) {
            int r0 = row0 + wm*32 + i*16 + g;
            int r1 = r0 + 8;
            *reinterpret_cast<float2*>(&out[(size_t)r0*Cc + cb]) =
                make_float2(c[i][j].x + bi.x, c[i][j].y + bi.y);
            *reinterpret_cast<float2*>(&out[(size_t)r1*Cc + cb]) =
                make_float2(c[i][j].z + bi.x, c[i][j].w + bi.y);
        }
    }
}

// ---------------------------------------------------------------------------
// Depthwise 5x5 conv (LEPE): float4/thread, branchless interior fast path.
// grid (Ll/4, Bb), 256 threads: tid>>6 -> one of 4 spatial positions, (tid&63)*4 -> channels
// ---------------------------------------------------------------------------
__global__ __launch_bounds__(256) void lepe_kernel(
    const float* __restrict__ wdw, const float* __restrict__ bdw)
{
    int tid = threadIdx.x;
    int c4 = (tid & 63) * 4;
    int l = blockIdx.x * 4 + (tid >> 6);
    int b = blockIdx.y;
    int h = l / Ww;
    int w = l - h*Ww;

    float4 acc = *reinterpret_cast<const float4*>(&bdw[c4]);
    const float* vb = g_v + (size_t)b*Ll*Cc;

    if (h >= 2 && h <= Hh-3 && w >= 2 && w <= Ww-3) {
        #pragma unroll
        for (int kh = 0; kh < 5; ++kh) {
            #pragma unroll
            for (int kw = 0; kw < 5; ++kw) {
                float4 vv = *reinterpret_cast<const float4*>(
                    &vb[((size_t)(h+kh-2)*Ww + (w+kw-2))*Cc + c4]);
                float4 wt = *reinterpret_cast<const float4*>(&wdw[(kh*5+kw)*Cc + c4]);
                acc.x = fmaf(vv.x, wt.x, acc.x);
                acc.y = fmaf(vv.y, wt.y, acc.y);
                acc.z = fmaf(vv.z, wt.z, acc.z);
                acc.w = fmaf(vv.w, wt.w, acc.w);
            }
        }
    } else {
        #pragma unroll
        for (int kh = 0; kh < 5; ++kh) {
            int hh = h + kh - 2;
            if ((unsigned)hh >= (unsigned)Hh) continue;
            #pragma unroll
            for (int kw = 0; kw < 5; ++kw) {
                int ww2 = w + kw - 2;
                if ((unsigned)ww2 >= (unsigned)Ww) continue;
                float4 vv = *reinterpret_cast<const float4*>(
                    &vb[((size_t)hh*Ww + ww2)*Cc + c4]);
                float4 wt = *reinterpret_cast<const float4*>(&wdw[(kh*5+kw)*Cc + c4]);
                acc.x = fmaf(vv.x, wt.x, acc.x);
                acc.y = fmaf(vv.y, wt.y, acc.y);
                acc.z = fmaf(vv.z, wt.z, acc.z);
                acc.w = fmaf(vv.w, wt.w, acc.w);
            }
        }
    }
    *reinterpret_cast<float4*>(&g_lepe[((size_t)b*Ll + l)*Cc + c4]) = acc;
}

// ---------------------------------------------------------------------------
// Flash attention, tf32 tensor cores; cp.async pipelines K/V (double-buffered)
// AND the mask tile (single-buffered, waited after QK mma).
// 256 threads = 8 warps; 128 Q rows/block; KV tiles of 64.
// dynamic smem: Ks[2][64][36] | Vs[2][64][40] | Ps[8][16][68] | Ms[128][68]
// ---------------------------------------------------------------------------
#define KS_OFF 0
#define VS_OFF (2*64*36)
#define PS_OFF (VS_OFF + 2*64*40)
#define MS_OFF (PS_OFF + 8*16*68)
#define SMEM_FLOATS (MS_OFF + 128*68)

__device__ __forceinline__ void cvt_inplace4(float* p) {
    float4 v = *reinterpret_cast<float4*>(p);
    v.x = f2tff(v.x); v.y = f2tff(v.y); v.z = f2tff(v.z); v.w = f2tff(v.w);
    *reinterpret_cast<float4*>(p) = v;
}

__global__ __launch_bounds__(256, 2) void attn_tc_kernel(const float* __restrict__ mask)
{
    extern __shared__ float sm[];
    float (*Ks)[64][36] = reinterpret_cast<float(*)[64][36]>(sm + KS_OFF);
    float (*Vs)[64][40] = reinterpret_cast<float(*)[64][40]>(sm + VS_OFF);
    float (*Ps)[16][68] = reinterpret_cast<float(*)[16][68]>(sm + PS_OFF);
    float (*Ms)[68]     = reinterpret_cast<float(*)[68]>(sm + MS_OFF);

    int tid  = threadIdx.x;
    int warp = tid >> 5, lane = tid & 31;
    int g = lane >> 2, t = lane & 3;
    int n = blockIdx.y >> 1, b = blockIdx.y & 1;
    int l0 = blockIdx.x * 128;
    int qrow = l0 + warp*16;

    const float* qb = g_q + ((size_t)(b*Ll + qrow))*Cc + n*HDd;
    const float* kb = g_k + ((size_t)b*Ll)*Cc + n*HDd;
    const float* vb = g_v + ((size_t)b*Ll)*Cc + n*HDd;
    const float* mbb = mask + ((size_t)n*Ll + l0)*Ll;   // block's 128 mask rows

    // persistent Q fragments (RNA tf32)
    unsigned qa[4][4];
    #pragma unroll
    for (int kc = 0; kc < 4; ++kc) {
        qa[kc][0] = f2tf(qb[(size_t)g*Cc     + kc*8 + t]);
        qa[kc][1] = f2tf(qb[(size_t)(g+8)*Cc + kc*8 + t]);
        qa[kc][2] = f2tf(qb[(size_t)g*Cc     + kc*8 + t + 4]);
        qa[kc][3] = f2tf(qb[(size_t)(g+8)*Cc + kc*8 + t + 4]);
    }

    // K/V staging coords: 4 cpa16 per thread per tile
    int sr = tid >> 3;            // 0..31
    int sc = (tid & 7) * 4;

    // prologue: kv tile 0 -> buf 0  (group KV0)
    cpa16(&Ks[0][sr   ][sc], &kb[(size_t)(sr   )*Cc + sc]);
    cpa16(&Ks[0][sr+32][sc], &kb[(size_t)(sr+32)*Cc + sc]);
    cpa16(&Vs[0][sr   ][sc], &vb[(size_t)(sr   )*Cc + sc]);
    cpa16(&Vs[0][sr+32][sc], &vb[(size_t)(sr+32)*Cc + sc]);
    CP_COMMIT();

    float mA = -1e30f, mB = -1e30f, lA = 0.f, lB = 0.f;
    float4 o[4] = {};

    for (int tile = 0; tile < Ll/64; ++tile) {
        int buf = tile & 1;
        int m0 = tile * 64;

        // stage mask tile (8 cpa16/thread): group M_i
        #pragma unroll
        for (int kk = 0; kk < 8; ++kk) {
            int oidx = tid + kk*256;          // 0..2047
            int mr = oidx >> 4, seg = (oidx & 15) * 4;
            cpa16(&Ms[mr][seg], &mbb[(size_t)mr*Ll + m0 + seg]);
        }
        CP_COMMIT();

        // stage next K/V tile: group KV_{i+1} (empty on last iter)
        if (m0 + 64 < Ll) {
            int nb0 = m0 + 64, ob = buf ^ 1;
            cpa16(&Ks[ob][sr   ][sc], &kb[(size_t)(nb0+sr   )*Cc + sc]);
            cpa16(&Ks[ob][sr+32][sc], &kb[(size_t)(nb0+sr+32)*Cc + sc]);
            cpa16(&Vs[ob][sr   ][sc], &vb[(size_t)(nb0+sr   )*Cc + sc]);
            cpa16(&Vs[ob][sr+32][sc], &vb[(size_t)(nb0+sr+32)*Cc + sc]);
        }
        CP_COMMIT();

        CP_WAIT2();   // KV_i complete (pending <= {M_i, KV_{i+1}})
        // convert own staged K/V regions to RNA tf32
        cvt_inplace4(&Ks[buf][sr   ][sc]);
        cvt_inplace4(&Ks[buf][sr+32][sc]);
        cvt_inplace4(&Vs[buf][sr   ][sc]);
        cvt_inplace4(&Vs[buf][sr+32][sc]);
        __syncthreads();

        // S = Q @ K^T  (16x64 per warp)
        float4 s[8];
        #pragma unroll
        for (int nb = 0; nb < 8; ++nb) {
            s[nb] = make_float4(0.f, 0.f, 0.f, 0.f);
            #pragma unroll
            for (int kc = 0; kc < 4; ++kc) {
                unsigned b0 = __float_as_uint(Ks[buf][nb*8+g][kc*8+t]);
                unsigned b1 = __float_as_uint(Ks[buf][nb*8+g][kc*8+t+4]);
                mma8(s[nb], qa[kc][0], qa[kc][1], qa[kc][2], qa[kc][3], b0, b1);
            }
        }

        CP_WAIT1();       // M_i complete (only KV_{i+1} may pend)
        __syncthreads();  // publish Ms to all threads

        // + mask (from smem), row-max
        int mrA = warp*16 + g, mrB = mrA + 8;
        float mxA = -1e30f, mxB = -1e30f;
        #pragma unroll
        for (int nb = 0; nb < 8; ++nb) {
            float2 ma = *reinterpret_cast<const float2*>(&Ms[mrA][nb*8 + 2*t]);
            float2 mc = *reinterpret_cast<const float2*>(&Ms[mrB][nb*8 + 2*t]);
            s[nb].x += ma.x; s[nb].y += ma.y;
            s[nb].z += mc.x; s[nb].w += mc.y;
            mxA = fmaxf(mxA, fmaxf(s[nb].x, s[nb].y));
            mxB = fmaxf(mxB, fmaxf(s[nb].z, s[nb].w));
        }
        mxA = fmaxf(mxA, __shfl_xor_sync(0xffffffffu, mxA, 1));
        mxA = fmaxf(mxA, __shfl_xor_sync(0xffffffffu, mxA, 2));
        mxB = fmaxf(mxB, __shfl_xor_sync(0xffffffffu, mxB, 1));
        mxB = fmaxf(mxB, __shfl_xor_sync(0xffffffffu, mxB, 2));

        float mAn = fmaxf(mA, mxA), mBn = fmaxf(mB, mxB);
        float scA = __expf(mA - mAn), scB = __expf(mB - mBn);
        mA = mAn; mB = mBn;

        // P = exp(S - m) -> smem (RNA tf32); row sums in fp32
        float sA = 0.f, sB = 0.f;
        #pragma unroll
        for (int nb = 0; nb < 8; ++nb) {
            float p0 = __expf(s[nb].x - mA);
            float p1 = __expf(s[nb].y - mA);
            float p2 = __expf(s[nb].z - mB);
            float p3 = __expf(s[nb].w - mB);
            sA += p0 + p1; sB += p2 + p3;
            Ps[warp][g  ][nb*8 + 2*t    ] = __uint_as_float(f2tf(p0));
            Ps[warp][g  ][nb*8 + 2*t + 1] = __uint_as_float(f2tf(p1));
            Ps[warp][g+8][nb*8 + 2*t    ] = __uint_as_float(f2tf(p2));
            Ps[warp][g+8][nb*8 + 2*t + 1] = __uint_as_float(f2tf(p3));
        }
        sA += __shfl_xor_sync(0xffffffffu, sA, 1);
        sA += __shfl_xor_sync(0xffffffffu, sA, 2);
        sB += __shfl_xor_sync(0xffffffffu, sB, 1);
        sB += __shfl_xor_sync(0xffffffffu, sB, 2);
        lA = lA*scA + sA;
        lB = lB*scB + sB;

        // rescale O
        #pragma unroll
        for (int nv = 0; nv < 4; ++nv) {
            o[nv].x *= scA; o[nv].y *= scA;
            o[nv].z *= scB; o[nv].w *= scB;
        }
        __syncwarp();

        // O += P @ V
        #pragma unroll
        for (int kc = 0; kc < 8; ++kc) {
            unsigned a0 = __float_as_uint(Ps[warp][g  ][kc*8 + t    ]);
            unsigned a1 = __float_as_uint(Ps[warp][g+8][kc*8 + t    ]);
            unsigned a2 = __float_as_uint(Ps[warp][g  ][kc*8 + t + 4]);
            unsigned a3 = __float_as_uint(Ps[warp][g+8][kc*8 + t + 4]);
            #pragma unroll
            for (int nv = 0; nv < 4; ++nv) {
                unsigned b0 = __float_as_uint(Vs[buf][kc*8 + t    ][nv*8 + g]);
                unsigned b1 = __float_as_uint(Vs[buf][kc*8 + t + 4][nv*8 + g]);
                mma8(o[nv], a0, a1, a2, a3, b0, b1);
            }
        }
        __syncthreads();   // all reads of Ms + Ks/Vs[buf] done before next-iter writes
    }

    float invA = 1.f / lA, invB = 1.f / lB;
    float* ob = g_attn + ((size_t)(b*Ll + qrow))*Cc + n*HDd;
    #pragma unroll
    for (int nv = 0; nv < 4; ++nv) {
        float2 wA = make_float2(o[nv].x*invA, o[nv].y*invA);
        float2 wB = make_float2(o[nv].z*invB, o[nv].w*invB);
        *reinterpret_cast<float2*>(&ob[(size_t)g*Cc     + nv*8 + 2*t]) = wA;
        *reinterpret_cast<float2*>(&ob[(size_t)(g+8)*Cc + nv*8 + 2*t]) = wB;
    }
}

// ---------------------------------------------------------------------------
extern "C" void kernel_launch(void* const* d_in, const int* in_sizes, int n_in,
                              void* d_out, int out_size)
{
    const float* x    = (const float*)d_in[0];
    const float* sinp = (const float*)d_in[1];
    const float* cosp = (const float*)d_in[2];
    const float* mask = (const float*)d_in[3];
    const float* wq   = (const float*)d_in[4];
    const float* bq   = (const float*)d_in[5];
    const float* wk   = (const float*)d_in[6];
    const float* bk   = (const float*)d_in[7];
    const float* wv   = (const float*)d_in[8];
    const float* bv   = (const float*)d_in[9];
    const float* wdw  = (const float*)d_in[10];
    const float* bdw  = (const float*)d_in[11];
    const float* wo   = (const float*)d_in[12];
    const float* bo   = (const float*)d_in[13];

    float *pa, *pl;
    cudaGetSymbolAddress((void**)&pa, g_attn);
    cudaGetSymbolAddress((void**)&pl, g_lepe);

    cudaFuncSetAttribute(attn_tc_kernel,
                         cudaFuncAttributeMaxDynamicSharedMemorySize,
                         SMEM_FLOATS * (int)sizeof(float));

    dim3 gg(Rr/64, Cc/64);
    qkv_tc_kernel<<<gg, 128>>>(x, wq, bq, wk, bk, wv, bv, sinp, cosp);

    lepe_kernel<<<dim3(Ll/4, Bb), 256>>>(wdw, bdw);

    attn_tc_kernel<<<dim3(Ll/128, Bb*NHh), 256, SMEM_FLOATS*sizeof(float)>>>(mask);

    gemm_tc_kernel<<<gg, 128>>>(pa, pl, wo, bo, (float*)d_out);
}